// round 7
// baseline (speedup 1.0000x reference)
#include <cuda_runtime.h>
#include <cuda_bf16.h>
#include <cstdint>
#include <math.h>

#define S_DIM 2048
#define B_DIM 32
#define H_DIM 1024
#define K_DIM 2048
#define M_DIM 65536

#define BM 128
#define BN 128
#define BKT 64
#define KTILES (K_DIM / BKT)     // 32
#define STAGES 3
#define THREADS 256              // 8 warps, 32x64 warp tiles
#define NTILES (H_DIM / BN)      // 8

// stage parts (bytes): Ah | Al | Bh | Bl, each 128 rows x 64 bf16 = 16KB
#define PART_A_H 0
#define PART_A_L 16384
#define PART_B_H 32768
#define PART_B_L 49152
#define STAGE_BYTES 65536
#define DSMEM_BYTES (STAGES * STAGE_BYTES)   // 192KB

// ---------------- device scratch ----------------
__device__ __nv_bfloat16 g_Ah[(size_t)M_DIM * K_DIM];
__device__ __nv_bfloat16 g_Al[(size_t)M_DIM * K_DIM];
__device__ __nv_bfloat16 g_Bh[(size_t)H_DIM * K_DIM];
__device__ __nv_bfloat16 g_Bl[(size_t)H_DIM * K_DIM];
__device__ float g_hpart[8 * B_DIM * H_DIM];  // e-slice partials [sl][b][h]
__device__ float g_hprojT[H_DIM * B_DIM];     // [h][b]
__device__ float g_part[NTILES * M_DIM];      // per-N-tile partial scores [nt][m]

// ---------------- PTX helpers (baseline sm_80+ only) ----------------
__device__ __forceinline__ uint32_t smem_u32(const void* p) {
    uint32_t a;
    asm("{ .reg .u64 t; cvta.to.shared.u64 t, %1; cvt.u32.u64 %0, t; }" : "=r"(a) : "l"(p));
    return a;
}
__device__ __forceinline__ void cp16(uint32_t dst, const void* src) {
    asm volatile("cp.async.cg.shared.global [%0], [%1], 16;" :: "r"(dst), "l"(src) : "memory");
}
__device__ __forceinline__ void cp_commit() {
    asm volatile("cp.async.commit_group;" ::: "memory");
}
__device__ __forceinline__ void cp_wait1() {
    asm volatile("cp.async.wait_group 1;" ::: "memory");
}
__device__ __forceinline__ void ldsm4(uint32_t* r, uint32_t addr) {
    asm volatile("ldmatrix.sync.aligned.m8n8.x4.shared.b16 {%0,%1,%2,%3}, [%4];"
                 : "=r"(r[0]), "=r"(r[1]), "=r"(r[2]), "=r"(r[3]) : "r"(addr));
}
__device__ __forceinline__ void mma_bf16(float* c, const uint32_t* a, uint32_t b0, uint32_t b1) {
    asm volatile("mma.sync.aligned.m16n8k16.row.col.f32.bf16.bf16.f32 "
                 "{%0,%1,%2,%3}, {%4,%5,%6,%7}, {%8,%9}, {%0,%1,%2,%3};"
                 : "+f"(c[0]), "+f"(c[1]), "+f"(c[2]), "+f"(c[3])
                 : "r"(a[0]), "r"(a[1]), "r"(a[2]), "r"(a[3]), "r"(b0), "r"(b1));
}

// swizzled 16B-unit offset inside a 128-row x 64-bf16 (128B-row) tile.
// c = 16B chunk column (0..7). XOR by row&7 -> conflict-free ldmatrix phases.
__device__ __forceinline__ uint32_t tile_off(int row, int c) {
    return (uint32_t)(((row << 3) + (c ^ (row & 7))) << 4);
}

// ---------------------------------------------------------------------------
// Pre-split A (enc, fp32) -> bf16 hi/lo
// ---------------------------------------------------------------------------
__global__ void asplit_kernel(const float* __restrict__ enc) {
    size_t g = ((size_t)blockIdx.x * 256 + threadIdx.x) * 8;
    float4 f0 = *reinterpret_cast<const float4*>(enc + g);
    float4 f1 = *reinterpret_cast<const float4*>(enc + g + 4);
    float x[8] = {f0.x, f0.y, f0.z, f0.w, f1.x, f1.y, f1.z, f1.w};
    uint32_t hh[4], ll[4];
#pragma unroll
    for (int i = 0; i < 4; i++) {
        __nv_bfloat162 h = __floats2bfloat162_rn(x[2 * i], x[2 * i + 1]);
        float2 hf = __bfloat1622float2(h);
        __nv_bfloat162 l = __floats2bfloat162_rn(x[2 * i] - hf.x, x[2 * i + 1] - hf.y);
        hh[i] = *reinterpret_cast<uint32_t*>(&h);
        ll[i] = *reinterpret_cast<uint32_t*>(&l);
    }
    *reinterpret_cast<uint4*>(&g_Ah[g]) = make_uint4(hh[0], hh[1], hh[2], hh[3]);
    *reinterpret_cast<uint4*>(&g_Al[g]) = make_uint4(ll[0], ll[1], ll[2], ll[3]);
}

// ---------------------------------------------------------------------------
// Pre-split + transpose We -> g_Bh/g_Bl [n][k]
// ---------------------------------------------------------------------------
__global__ void bsplit_kernel(const float* __restrict__ W) {
    __shared__ float tile[32][33];
    const int k0 = blockIdx.x * 32;
    const int n0 = blockIdx.y * 32;
    const int tx = threadIdx.x;
    const int ty = threadIdx.y;
#pragma unroll
    for (int r = 0; r < 4; r++) {
        int k = ty * 4 + r;
        tile[k][tx] = W[(size_t)(H_DIM + k0 + k) * H_DIM + n0 + tx];
    }
    __syncthreads();
#pragma unroll
    for (int r = 0; r < 4; r++) {
        int n = ty * 4 + r;
        float w = tile[tx][n];
        __nv_bfloat16 h = __float2bfloat16_rn(w);
        float l = w - __bfloat162float(h);
        size_t o = (size_t)(n0 + n) * K_DIM + k0 + tx;
        g_Bh[o] = h;
        g_Bl[o] = __float2bfloat16_rn(l);
    }
}

// ---------------------------------------------------------------------------
// hproj stage 1 + 2
// ---------------------------------------------------------------------------
__global__ void hproj1_kernel(const float* __restrict__ hidden,
                              const float* __restrict__ W) {
    const int b  = blockIdx.x;
    const int sl = blockIdx.y;
    const int h4 = threadIdx.x * 4;
    const float* hr = hidden + b * H_DIM + sl * 128;
    float4 acc = make_float4(0.f, 0.f, 0.f, 0.f);
#pragma unroll 8
    for (int e = 0; e < 128; e++) {
        float f = hr[e];
        float4 w = *reinterpret_cast<const float4*>(
            &W[(size_t)(sl * 128 + e) * H_DIM + h4]);
        acc.x += f * w.x; acc.y += f * w.y; acc.z += f * w.z; acc.w += f * w.w;
    }
    *reinterpret_cast<float4*>(&g_hpart[((size_t)sl * B_DIM + b) * H_DIM + h4]) = acc;
}

__global__ void hproj2_kernel(const float* __restrict__ bias) {
    int g = blockIdx.x * 256 + threadIdx.x;
    int b = g >> 8;
    int h4 = (g & 255) * 4;
    float4 acc = make_float4(bias[h4], bias[h4 + 1], bias[h4 + 2], bias[h4 + 3]);
#pragma unroll
    for (int sl = 0; sl < 8; sl++) {
        float4 p = *reinterpret_cast<const float4*>(
            &g_hpart[((size_t)sl * B_DIM + b) * H_DIM + h4]);
        acc.x += p.x; acc.y += p.y; acc.z += p.z; acc.w += p.w;
    }
    g_hprojT[(h4 + 0) * B_DIM + b] = acc.x;
    g_hprojT[(h4 + 1) * B_DIM + b] = acc.y;
    g_hprojT[(h4 + 2) * B_DIM + b] = acc.z;
    g_hprojT[(h4 + 3) * B_DIM + b] = acc.w;
}

// ---------------------------------------------------------------------------
// HMMA GEMM + fused tanh/v epilogue.
// 1 CTA/SM, 256 threads, 8 warps of 32(M)x64(N). BKT=64, 3-stage cp.async.
// grid (8 Ntiles, 512 Mtiles).
// ---------------------------------------------------------------------------
__global__ __launch_bounds__(THREADS, 1)
void score_kernel(const float* __restrict__ v) {
    extern __shared__ char dsm[];
    const int tid  = threadIdx.x;
    const int wid  = tid >> 5;
    const int lane = tid & 31;
    const int Mo = blockIdx.y * BM;
    const int No = blockIdx.x * BN;

    const int wm = (wid & 3) * 32;     // warp M offset
    const int wn = (wid >> 2) * 64;    // warp N offset

    // ldmatrix offsets: ks in 0..3 selects 16 bf16 cols = chunk cols {2ks, 2ks+1}
    const int lrow = lane & 15, lk = lane >> 4;
    uint32_t aoff[2][4], boff[4][4];
#pragma unroll
    for (int ks = 0; ks < 4; ks++) {
#pragma unroll
        for (int mt = 0; mt < 2; mt++)
            aoff[mt][ks] = tile_off(wm + mt * 16 + lrow, 2 * ks + lk);
#pragma unroll
        for (int nb = 0; nb < 4; nb++)
            boff[nb][ks] = tile_off(wn + nb * 16 + lrow, 2 * ks + lk);
    }

    // cp.async: 1024 16B-chunks per part, 4 per thread
    const char* pA[4];
    const char* pB[4];
    uint32_t so[4];
#pragma unroll
    for (int i = 0; i < 4; i++) {
        int idx = tid + i * 256;
        int row = idx >> 3, c = idx & 7;
        so[i] = tile_off(row, c);
        pA[i] = reinterpret_cast<const char*>(&g_Ah[(size_t)(Mo + row) * K_DIM + c * 8]);
        pB[i] = reinterpret_cast<const char*>(&g_Bh[(size_t)(No + row) * K_DIM + c * 8]);
    }
    const size_t dAL = (const char*)g_Al - (const char*)g_Ah;
    const size_t dBL = (const char*)g_Bl - (const char*)g_Bh;

    const uint32_t smb = smem_u32(dsm);
    float acc[2][8][4];
#pragma unroll
    for (int mt = 0; mt < 2; mt++)
#pragma unroll
        for (int nt = 0; nt < 8; nt++)
#pragma unroll
            for (int i = 0; i < 4; i++) acc[mt][nt][i] = 0.f;

    auto load_stage = [&](int slot) {
        uint32_t sb = smb + slot * STAGE_BYTES;
#pragma unroll
        for (int i = 0; i < 4; i++) {
            cp16(sb + PART_A_H + so[i], pA[i]);
            cp16(sb + PART_A_L + so[i], pA[i] + dAL);
            cp16(sb + PART_B_H + so[i], pB[i]);
            cp16(sb + PART_B_L + so[i], pB[i] + dBL);
        }
#pragma unroll
        for (int i = 0; i < 4; i++) { pA[i] += 128; pB[i] += 128; }
    };

    load_stage(0); cp_commit();
    load_stage(1); cp_commit();
    cp_wait1();
    __syncthreads();

    int slot_ld = 2, slot_cp = 0;
    for (int kt = 0; kt < KTILES; kt++) {
        if (kt + STAGES - 1 < KTILES) load_stage(slot_ld);
        cp_commit();
        if (++slot_ld == STAGES) slot_ld = 0;

        uint32_t AH = smb + slot_cp * STAGE_BYTES + PART_A_H;
        uint32_t AL = smb + slot_cp * STAGE_BYTES + PART_A_L;
        uint32_t BH = smb + slot_cp * STAGE_BYTES + PART_B_H;
        uint32_t BL = smb + slot_cp * STAGE_BYTES + PART_B_L;
        if (++slot_cp == STAGES) slot_cp = 0;

#pragma unroll
        for (int ks = 0; ks < 4; ks++) {
            uint32_t ah0[4], ah1[4], bq[4][4];
            ldsm4(ah0, AH + aoff[0][ks]);
            ldsm4(ah1, AH + aoff[1][ks]);
#pragma unroll
            for (int nb = 0; nb < 4; nb++) ldsm4(bq[nb], BH + boff[nb][ks]);
#pragma unroll
            for (int nt = 0; nt < 8; nt++) {
                uint32_t b0 = bq[nt >> 1][nt & 1];
                uint32_t b1 = bq[nt >> 1][(nt & 1) + 2];
                mma_bf16(acc[0][nt], ah0, b0, b1);
                mma_bf16(acc[1][nt], ah1, b0, b1);
            }
            // Al * Bh  (Bh fragments live)
            uint32_t al0[4], al1[4];
            ldsm4(al0, AL + aoff[0][ks]);
            ldsm4(al1, AL + aoff[1][ks]);
#pragma unroll
            for (int nt = 0; nt < 8; nt++) {
                uint32_t b0 = bq[nt >> 1][nt & 1];
                uint32_t b1 = bq[nt >> 1][(nt & 1) + 2];
                mma_bf16(acc[0][nt], al0, b0, b1);
                mma_bf16(acc[1][nt], al1, b0, b1);
            }
            // Ah * Bl  (Ah live; Bl in fresh regs)
            uint32_t cq[4][4];
#pragma unroll
            for (int nb = 0; nb < 4; nb++) ldsm4(cq[nb], BL + boff[nb][ks]);
#pragma unroll
            for (int nt = 0; nt < 8; nt++) {
                uint32_t b0 = cq[nt >> 1][nt & 1];
                uint32_t b1 = cq[nt >> 1][(nt & 1) + 2];
                mma_bf16(acc[0][nt], ah0, b0, b1);
                mma_bf16(acc[1][nt], ah1, b0, b1);
            }
        }
        cp_wait1();
        __syncthreads();
    }

    // ---- epilogue ----
    float* hp_s = reinterpret_cast<float*>(dsm);           // [128][33]
    float* v_s  = reinterpret_cast<float*>(dsm + 128 * 33 * 4);
    float* red  = v_s + 128;                               // [2][128]
    __syncthreads();
    for (int i = tid; i < 128 * 32; i += THREADS) {
        int nl = i >> 5, b = i & 31;
        hp_s[nl * 33 + b] = g_hprojT[(No + nl) * B_DIM + b];
    }
    if (tid < 128) v_s[tid] = v[No + tid];
    __syncthreads();

#pragma unroll
    for (int mt = 0; mt < 2; mt++) {
        int r0 = Mo + wm + mt * 16 + (lane >> 2);
        int b0r = r0 & 31, b1r = (r0 + 8) & 31;
        float s0 = 0.f, s1 = 0.f;
#pragma unroll
        for (int nt = 0; nt < 8; nt++) {
            int nl = wn + nt * 8 + (lane & 3) * 2;
            float vv0 = v_s[nl], vv1 = v_s[nl + 1];
            s0 += vv0 * tanhf(acc[mt][nt][0] + hp_s[nl * 33 + b0r]);
            s0 += vv1 * tanhf(acc[mt][nt][1] + hp_s[(nl + 1) * 33 + b0r]);
            s1 += vv0 * tanhf(acc[mt][nt][2] + hp_s[nl * 33 + b1r]);
            s1 += vv1 * tanhf(acc[mt][nt][3] + hp_s[(nl + 1) * 33 + b1r]);
        }
        s0 += __shfl_xor_sync(0xffffffffu, s0, 1);
        s0 += __shfl_xor_sync(0xffffffffu, s0, 2);
        s1 += __shfl_xor_sync(0xffffffffu, s1, 1);
        s1 += __shfl_xor_sync(0xffffffffu, s1, 2);
        if ((lane & 3) == 0) {
            int rl = wm + mt * 16 + (lane >> 2);
            red[(wid >> 2) * 128 + rl] = s0;
            red[(wid >> 2) * 128 + rl + 8] = s1;
        }
    }
    __syncthreads();
    if (tid < 128)
        g_part[(size_t)blockIdx.x * M_DIM + Mo + tid] = red[tid] + red[128 + tid];
}

// ---------------------------------------------------------------------------
// softmax: sum 8 N-tile partials, softmax over S per batch row
// ---------------------------------------------------------------------------
__global__ void softmax_kernel(float* __restrict__ out) {
    __shared__ float srow[S_DIM];
    __shared__ float rd[256];
    const int b = blockIdx.x;
    const int t = threadIdx.x;

    float m = -INFINITY;
    for (int i = t; i < S_DIM; i += 256) {
        int mm = i * B_DIM + b;
        float sc = 0.f;
#pragma unroll
        for (int nt = 0; nt < NTILES; nt++) sc += g_part[(size_t)nt * M_DIM + mm];
        srow[i] = sc;
        m = fmaxf(m, sc);
    }
    rd[t] = m;
    __syncthreads();
    for (int o = 128; o > 0; o >>= 1) { if (t < o) rd[t] = fmaxf(rd[t], rd[t + o]); __syncthreads(); }
    m = rd[0];
    __syncthreads();

    float sum = 0.f;
    for (int i = t; i < S_DIM; i += 256) {
        float e = expf(srow[i] - m);
        srow[i] = e;
        sum += e;
    }
    rd[t] = sum;
    __syncthreads();
    for (int o = 128; o > 0; o >>= 1) { if (t < o) rd[t] += rd[t + o]; __syncthreads(); }
    float inv = 1.f / rd[0];
    __syncthreads();
    float* orow = out + (size_t)b * S_DIM;
    for (int i = t; i < S_DIM; i += 256) orow[i] = srow[i] * inv;
}

// ---------------------------------------------------------------------------
extern "C" void kernel_launch(void* const* d_in, const int* in_sizes, int n_in,
                              void* d_out, int out_size) {
    const float* hidden = (const float*)d_in[0];
    const float* enc    = (const float*)d_in[1];
    const float* W      = (const float*)d_in[2];
    const float* bias   = (const float*)d_in[3];
    const float* v      = (const float*)d_in[4];
    float* out = (float*)d_out;

    cudaFuncSetAttribute(score_kernel, cudaFuncAttributeMaxDynamicSharedMemorySize, DSMEM_BYTES);

    asplit_kernel<<<M_DIM * K_DIM / 2048, 256>>>(enc);
    bsplit_kernel<<<dim3(K_DIM / 32, H_DIM / 32), dim3(32, 8)>>>(W);
    hproj1_kernel<<<dim3(B_DIM, 8), 256>>>(hidden, W);
    hproj2_kernel<<<32, 256>>>(bias);
    score_kernel<<<dim3(NTILES, M_DIM / BM), THREADS, DSMEM_BYTES>>>(v);
    softmax_kernel<<<B_DIM, 256>>>(out);
}

// round 8
// speedup vs baseline: 1.0539x; 1.0539x over previous
#include <cuda_runtime.h>
#include <cuda_bf16.h>
#include <cstdint>
#include <math.h>

#define S_DIM 2048
#define B_DIM 32
#define H_DIM 1024
#define K_DIM 2048
#define M_DIM 65536

#define BM 128
#define BN 128
#define BKT 32
#define KTILES (K_DIM / BKT)     // 64
#define STAGES 3
#define THREADS 256
#define NTILES (H_DIM / BN)      // 8

// stage parts (bytes): Ah | Al | Bh | Bl, each 128 rows x 32 bf16 = 8KB
#define PART_A_H 0
#define PART_A_L 8192
#define PART_B_H 16384
#define PART_B_L 24576
#define STAGE_BYTES 32768
#define DSMEM_BYTES (STAGES * STAGE_BYTES)

// ---------------- device scratch ----------------
__device__ __nv_bfloat16 g_Ah[(size_t)M_DIM * K_DIM];
__device__ __nv_bfloat16 g_Al[(size_t)M_DIM * K_DIM];
__device__ __nv_bfloat16 g_Bh[(size_t)H_DIM * K_DIM];
__device__ __nv_bfloat16 g_Bl[(size_t)H_DIM * K_DIM];
__device__ float g_hpart[8 * B_DIM * H_DIM];  // e-slice partials [sl][b][h]
__device__ float g_hprojT[H_DIM * B_DIM];     // [h][b]
__device__ float g_part[NTILES * M_DIM];      // per-N-tile partial scores [nt][m]

// ---------------- PTX helpers (baseline sm_80+ only) ----------------
__device__ __forceinline__ uint32_t smem_u32(const void* p) {
    uint32_t a;
    asm("{ .reg .u64 t; cvta.to.shared.u64 t, %1; cvt.u32.u64 %0, t; }" : "=r"(a) : "l"(p));
    return a;
}
__device__ __forceinline__ void cp16(uint32_t dst, const void* src) {
    asm volatile("cp.async.cg.shared.global [%0], [%1], 16;" :: "r"(dst), "l"(src) : "memory");
}
__device__ __forceinline__ void cp_commit() {
    asm volatile("cp.async.commit_group;" ::: "memory");
}
__device__ __forceinline__ void cp_wait1() {
    asm volatile("cp.async.wait_group 1;" ::: "memory");
}
__device__ __forceinline__ void ldsm4(uint32_t* r, uint32_t addr) {
    asm volatile("ldmatrix.sync.aligned.m8n8.x4.shared.b16 {%0,%1,%2,%3}, [%4];"
                 : "=r"(r[0]), "=r"(r[1]), "=r"(r[2]), "=r"(r[3]) : "r"(addr));
}
__device__ __forceinline__ void mma_bf16(float* c, const uint32_t* a, uint32_t b0, uint32_t b1) {
    asm volatile("mma.sync.aligned.m16n8k16.row.col.f32.bf16.bf16.f32 "
                 "{%0,%1,%2,%3}, {%4,%5,%6,%7}, {%8,%9}, {%0,%1,%2,%3};"
                 : "+f"(c[0]), "+f"(c[1]), "+f"(c[2]), "+f"(c[3])
                 : "r"(a[0]), "r"(a[1]), "r"(a[2]), "r"(a[3]), "r"(b0), "r"(b1));
}

// swizzled 16B-unit offset inside a 128x32 bf16 tile
__device__ __forceinline__ uint32_t tile_off(int row, int c) {
    return (uint32_t)(((row << 2) + (c ^ ((row >> 1) & 3))) << 4);
}

// ---------------------------------------------------------------------------
// prep: fused bsplit (blocks [0,2048)) + hproj1 (blocks [2048,2304))
// ---------------------------------------------------------------------------
__global__ void prep_kernel(const float* __restrict__ W,
                            const float* __restrict__ hidden) {
    __shared__ float tile[32][33];
    const int bid = blockIdx.x;
    const int t = threadIdx.x;

    if (bid < 2048) {
        // ---- bsplit: transpose + split We tile (32k x 32n) ----
        const int k0 = (bid & 63) * 32;
        const int n0 = (bid >> 6) * 32;
        const int tx = t & 31;
        const int ty = t >> 5;           // 0..7
#pragma unroll
        for (int r = 0; r < 4; r++) {
            int k = ty * 4 + r;
            tile[k][tx] = W[(size_t)(H_DIM + k0 + k) * H_DIM + n0 + tx];
        }
        __syncthreads();
#pragma unroll
        for (int r = 0; r < 4; r++) {
            int n = ty * 4 + r;
            float w = tile[tx][n];
            __nv_bfloat16 h = __float2bfloat16_rn(w);
            float l = w - __bfloat162float(h);
            size_t o = (size_t)(n0 + n) * K_DIM + k0 + tx;
            g_Bh[o] = h;
            g_Bl[o] = __float2bfloat16_rn(l);
        }
    } else {
        // ---- hproj1: e-slice partials ----
        const int idx = bid - 2048;      // 0..255
        const int b  = idx & 31;
        const int sl = idx >> 5;         // 0..7
        const int h4 = t * 4;
        const float* hr = hidden + b * H_DIM + sl * 128;
        float4 acc = make_float4(0.f, 0.f, 0.f, 0.f);
#pragma unroll 8
        for (int e = 0; e < 128; e++) {
            float f = hr[e];
            float4 w = *reinterpret_cast<const float4*>(
                &W[(size_t)(sl * 128 + e) * H_DIM + h4]);
            acc.x += f * w.x; acc.y += f * w.y; acc.z += f * w.z; acc.w += f * w.w;
        }
        *reinterpret_cast<float4*>(&g_hpart[((size_t)sl * B_DIM + b) * H_DIM + h4]) = acc;
    }
}

// ---------------------------------------------------------------------------
// hproj stage 2: combine slices + bias, store transposed [h][b]
// ---------------------------------------------------------------------------
__global__ void hproj2_kernel(const float* __restrict__ bias) {
    int g = blockIdx.x * 256 + threadIdx.x;
    int b = g >> 8;
    int h4 = (g & 255) * 4;
    float4 acc = make_float4(bias[h4], bias[h4 + 1], bias[h4 + 2], bias[h4 + 3]);
#pragma unroll
    for (int sl = 0; sl < 8; sl++) {
        float4 p = *reinterpret_cast<const float4*>(
            &g_hpart[((size_t)sl * B_DIM + b) * H_DIM + h4]);
        acc.x += p.x; acc.y += p.y; acc.z += p.z; acc.w += p.w;
    }
    g_hprojT[(h4 + 0) * B_DIM + b] = acc.x;
    g_hprojT[(h4 + 1) * B_DIM + b] = acc.y;
    g_hprojT[(h4 + 2) * B_DIM + b] = acc.z;
    g_hprojT[(h4 + 3) * B_DIM + b] = acc.w;
}

// ---------------------------------------------------------------------------
// Pre-split A (enc, fp32) -> bf16 hi/lo
// ---------------------------------------------------------------------------
__global__ void asplit_kernel(const float* __restrict__ enc) {
    size_t g = ((size_t)blockIdx.x * 256 + threadIdx.x) * 8;
    float4 f0 = *reinterpret_cast<const float4*>(enc + g);
    float4 f1 = *reinterpret_cast<const float4*>(enc + g + 4);
    float x[8] = {f0.x, f0.y, f0.z, f0.w, f1.x, f1.y, f1.z, f1.w};
    uint32_t hh[4], ll[4];
#pragma unroll
    for (int i = 0; i < 4; i++) {
        __nv_bfloat162 h = __floats2bfloat162_rn(x[2 * i], x[2 * i + 1]);
        float2 hf = __bfloat1622float2(h);
        __nv_bfloat162 l = __floats2bfloat162_rn(x[2 * i] - hf.x, x[2 * i + 1] - hf.y);
        hh[i] = *reinterpret_cast<uint32_t*>(&h);
        ll[i] = *reinterpret_cast<uint32_t*>(&l);
    }
    *reinterpret_cast<uint4*>(&g_Ah[g]) = make_uint4(hh[0], hh[1], hh[2], hh[3]);
    *reinterpret_cast<uint4*>(&g_Al[g]) = make_uint4(ll[0], ll[1], ll[2], ll[3]);
}

// ---------------------------------------------------------------------------
// HMMA GEMM + fused tanh/v epilogue (R5 best config).
// grid (8 Ntiles, 512 Mtiles), 256 threads, 2 CTA/SM, 32x64 warp tiles.
// C[m][n] over K via 3 bf16 term-pairs: AhBh + AlBh + AhBl.
// ---------------------------------------------------------------------------
__global__ __launch_bounds__(THREADS, 2)
void score_kernel(const float* __restrict__ v) {
    extern __shared__ char dsm[];
    const int tid  = threadIdx.x;
    const int wid  = tid >> 5;
    const int lane = tid & 31;
    const int Mo = blockIdx.y * BM;
    const int No = blockIdx.x * BN;

    const int wm = (wid & 3) * 32;     // warp M offset in tile
    const int wn = (wid >> 2) * 64;    // warp N offset in tile

    // precomputed ldmatrix offsets
    const int lrow = lane & 15, lk = lane >> 4;
    uint32_t aoff[2][2], boff[4][2];
#pragma unroll
    for (int ks = 0; ks < 2; ks++) {
#pragma unroll
        for (int mt = 0; mt < 2; mt++)
            aoff[mt][ks] = tile_off(wm + mt * 16 + lrow, ks * 2 + lk);
#pragma unroll
        for (int nb = 0; nb < 4; nb++)
            boff[nb][ks] = tile_off(wn + nb * 16 + lrow, ks * 2 + lk);
    }

    // precomputed cp.async pointers (advance +64B per kt) and smem offsets
    const char* pA[2];
    const char* pB[2];
    uint32_t so[2];
#pragma unroll
    for (int i = 0; i < 2; i++) {
        int idx = tid + i * 256;
        int row = idx >> 2, c = idx & 3;
        so[i] = tile_off(row, c);
        pA[i] = reinterpret_cast<const char*>(&g_Ah[(size_t)(Mo + row) * K_DIM + c * 8]);
        pB[i] = reinterpret_cast<const char*>(&g_Bh[(size_t)(No + row) * K_DIM + c * 8]);
    }
    const size_t dAL = (const char*)g_Al - (const char*)g_Ah;
    const size_t dBL = (const char*)g_Bl - (const char*)g_Bh;

    const uint32_t smb = smem_u32(dsm);
    float acc[2][8][4];
#pragma unroll
    for (int mt = 0; mt < 2; mt++)
#pragma unroll
        for (int nt = 0; nt < 8; nt++)
#pragma unroll
            for (int i = 0; i < 4; i++) acc[mt][nt][i] = 0.f;

    auto load_stage = [&](int slot) {
        uint32_t sb = smb + slot * STAGE_BYTES;
#pragma unroll
        for (int i = 0; i < 2; i++) {
            cp16(sb + PART_A_H + so[i], pA[i]);
            cp16(sb + PART_A_L + so[i], pA[i] + dAL);
            cp16(sb + PART_B_H + so[i], pB[i]);
            cp16(sb + PART_B_L + so[i], pB[i] + dBL);
        }
        pA[0] += 64; pA[1] += 64; pB[0] += 64; pB[1] += 64;
    };

    // prologue
    load_stage(0); cp_commit();
    load_stage(1); cp_commit();
    cp_wait1();
    __syncthreads();

    int slot_ld = 2, slot_cp = 0;
    for (int kt = 0; kt < KTILES; kt++) {
        if (kt + STAGES - 1 < KTILES) load_stage(slot_ld);
        cp_commit();
        if (++slot_ld == STAGES) slot_ld = 0;

        uint32_t AH = smb + slot_cp * STAGE_BYTES + PART_A_H;
        uint32_t AL = smb + slot_cp * STAGE_BYTES + PART_A_L;
        uint32_t BH = smb + slot_cp * STAGE_BYTES + PART_B_H;
        uint32_t BL = smb + slot_cp * STAGE_BYTES + PART_B_L;
        if (++slot_cp == STAGES) slot_cp = 0;

#pragma unroll
        for (int ks = 0; ks < 2; ks++) {
            uint32_t ah0[4], ah1[4], bq[4][4];
            ldsm4(ah0, AH + aoff[0][ks]);
            ldsm4(ah1, AH + aoff[1][ks]);
#pragma unroll
            for (int nb = 0; nb < 4; nb++) ldsm4(bq[nb], BH + boff[nb][ks]);
#pragma unroll
            for (int nt = 0; nt < 8; nt++) {
                uint32_t b0 = bq[nt >> 1][nt & 1];
                uint32_t b1 = bq[nt >> 1][(nt & 1) + 2];
                mma_bf16(acc[0][nt], ah0, b0, b1);
                mma_bf16(acc[1][nt], ah1, b0, b1);
            }
            // Al * Bh  (Bh fragments live)
            uint32_t al0[4], al1[4];
            ldsm4(al0, AL + aoff[0][ks]);
            ldsm4(al1, AL + aoff[1][ks]);
#pragma unroll
            for (int nt = 0; nt < 8; nt++) {
                uint32_t b0 = bq[nt >> 1][nt & 1];
                uint32_t b1 = bq[nt >> 1][(nt & 1) + 2];
                mma_bf16(acc[0][nt], al0, b0, b1);
                mma_bf16(acc[1][nt], al1, b0, b1);
            }
            // Ah * Bl  (Ah live; Bl in fresh regs)
            uint32_t cq[4][4];
#pragma unroll
            for (int nb = 0; nb < 4; nb++) ldsm4(cq[nb], BL + boff[nb][ks]);
#pragma unroll
            for (int nt = 0; nt < 8; nt++) {
                uint32_t b0 = cq[nt >> 1][nt & 1];
                uint32_t b1 = cq[nt >> 1][(nt & 1) + 2];
                mma_bf16(acc[0][nt], ah0, b0, b1);
                mma_bf16(acc[1][nt], ah1, b0, b1);
            }
        }
        cp_wait1();
        __syncthreads();
    }

    // ---- epilogue ----
    float* hp_s = reinterpret_cast<float*>(dsm);           // [128][33]
    float* v_s  = reinterpret_cast<float*>(dsm + 128 * 33 * 4);
    float* red  = v_s + 128;                               // [2][128]
    __syncthreads();
    for (int i = tid; i < 128 * 32; i += THREADS) {
        int nl = i >> 5, b = i & 31;
        hp_s[nl * 33 + b] = g_hprojT[(No + nl) * B_DIM + b];
    }
    if (tid < 128) v_s[tid] = v[No + tid];
    __syncthreads();

#pragma unroll
    for (int mt = 0; mt < 2; mt++) {
        int r0 = Mo + wm + mt * 16 + (lane >> 2);
        int b0r = r0 & 31, b1r = (r0 + 8) & 31;
        float s0 = 0.f, s1 = 0.f;
#pragma unroll
        for (int nt = 0; nt < 8; nt++) {
            int nl = wn + nt * 8 + (lane & 3) * 2;
            float vv0 = v_s[nl], vv1 = v_s[nl + 1];
            s0 += vv0 * tanhf(acc[mt][nt][0] + hp_s[nl * 33 + b0r]);
            s0 += vv1 * tanhf(acc[mt][nt][1] + hp_s[(nl + 1) * 33 + b0r]);
            s1 += vv0 * tanhf(acc[mt][nt][2] + hp_s[nl * 33 + b1r]);
            s1 += vv1 * tanhf(acc[mt][nt][3] + hp_s[(nl + 1) * 33 + b1r]);
        }
        s0 += __shfl_xor_sync(0xffffffffu, s0, 1);
        s0 += __shfl_xor_sync(0xffffffffu, s0, 2);
        s1 += __shfl_xor_sync(0xffffffffu, s1, 1);
        s1 += __shfl_xor_sync(0xffffffffu, s1, 2);
        if ((lane & 3) == 0) {
            int rl = wm + mt * 16 + (lane >> 2);
            red[(wid >> 2) * 128 + rl] = s0;
            red[(wid >> 2) * 128 + rl + 8] = s1;
        }
    }
    __syncthreads();
    if (tid < 128)
        g_part[(size_t)blockIdx.x * M_DIM + Mo + tid] = red[tid] + red[128 + tid];
}

// ---------------------------------------------------------------------------
// softmax: sum 8 N-tile partials, softmax over S per batch row
// ---------------------------------------------------------------------------
__global__ void softmax_kernel(float* __restrict__ out) {
    __shared__ float srow[S_DIM];
    __shared__ float rd[256];
    const int b = blockIdx.x;
    const int t = threadIdx.x;

    float m = -INFINITY;
    for (int i = t; i < S_DIM; i += 256) {
        int mm = i * B_DIM + b;
        float sc = 0.f;
#pragma unroll
        for (int nt = 0; nt < NTILES; nt++) sc += g_part[(size_t)nt * M_DIM + mm];
        srow[i] = sc;
        m = fmaxf(m, sc);
    }
    rd[t] = m;
    __syncthreads();
    for (int o = 128; o > 0; o >>= 1) { if (t < o) rd[t] = fmaxf(rd[t], rd[t + o]); __syncthreads(); }
    m = rd[0];
    __syncthreads();

    float sum = 0.f;
    for (int i = t; i < S_DIM; i += 256) {
        float e = expf(srow[i] - m);
        srow[i] = e;
        sum += e;
    }
    rd[t] = sum;
    __syncthreads();
    for (int o = 128; o > 0; o >>= 1) { if (t < o) rd[t] += rd[t + o]; __syncthreads(); }
    float inv = 1.f / rd[0];
    __syncthreads();
    float* orow = out + (size_t)b * S_DIM;
    for (int i = t; i < S_DIM; i += 256) orow[i] = srow[i] * inv;
}

// ---------------------------------------------------------------------------
extern "C" void kernel_launch(void* const* d_in, const int* in_sizes, int n_in,
                              void* d_out, int out_size) {
    const float* hidden = (const float*)d_in[0];
    const float* enc    = (const float*)d_in[1];
    const float* W      = (const float*)d_in[2];
    const float* bias   = (const float*)d_in[3];
    const float* v      = (const float*)d_in[4];
    float* out = (float*)d_out;

    cudaFuncSetAttribute(score_kernel, cudaFuncAttributeMaxDynamicSharedMemorySize, DSMEM_BYTES);

    prep_kernel<<<2304, 256>>>(W, hidden);                 // launch 0
    hproj2_kernel<<<32, 256>>>(bias);                      // launch 1
    asplit_kernel<<<M_DIM * K_DIM / 2048, 256>>>(enc);     // launch 2
    score_kernel<<<dim3(NTILES, M_DIM / BM), THREADS, DSMEM_BYTES>>>(v);  // launch 3 (profiled)
    softmax_kernel<<<B_DIM, 256>>>(out);                   // launch 4
}

// round 9
// speedup vs baseline: 1.0609x; 1.0066x over previous
#include <cuda_runtime.h>
#include <cuda_bf16.h>
#include <cstdint>
#include <math.h>

#define S_DIM 2048
#define B_DIM 32
#define H_DIM 1024
#define K_DIM 2048
#define M_DIM 65536

#define BM 128
#define BN 128
#define BKT 32
#define KTILES (K_DIM / BKT)     // 64
#define STAGES 3
#define THREADS 256
#define NTILES (H_DIM / BN)      // 8

// stage parts (bytes): Ah | Al | Bh | Bl, each 128 rows x 32 bf16 = 8KB
#define PART_A_H 0
#define PART_A_L 8192
#define PART_B_H 16384
#define PART_B_L 24576
#define STAGE_BYTES 32768
#define DSMEM_BYTES (STAGES * STAGE_BYTES)

// ---------------- device scratch ----------------
__device__ __nv_bfloat16 g_Ah[(size_t)M_DIM * K_DIM];
__device__ __nv_bfloat16 g_Al[(size_t)M_DIM * K_DIM];
__device__ __nv_bfloat16 g_Bh[(size_t)H_DIM * K_DIM];
__device__ __nv_bfloat16 g_Bl[(size_t)H_DIM * K_DIM];
__device__ float g_hpart[8 * B_DIM * H_DIM];  // e-slice partials [sl][b][h]
__device__ float g_hprojT[H_DIM * B_DIM];     // [h][b]
__device__ float g_part[NTILES * M_DIM];      // per-N-tile partial scores [nt][m]

// ---------------- PTX helpers (baseline sm_80+ only) ----------------
__device__ __forceinline__ uint32_t smem_u32(const void* p) {
    uint32_t a;
    asm("{ .reg .u64 t; cvta.to.shared.u64 t, %1; cvt.u32.u64 %0, t; }" : "=r"(a) : "l"(p));
    return a;
}
__device__ __forceinline__ void cp16(uint32_t dst, const void* src) {
    asm volatile("cp.async.cg.shared.global [%0], [%1], 16;" :: "r"(dst), "l"(src) : "memory");
}
__device__ __forceinline__ void cp_commit() {
    asm volatile("cp.async.commit_group;" ::: "memory");
}
__device__ __forceinline__ void cp_wait1() {
    asm volatile("cp.async.wait_group 1;" ::: "memory");
}
__device__ __forceinline__ void ldsm4(uint32_t* r, uint32_t addr) {
    asm volatile("ldmatrix.sync.aligned.m8n8.x4.shared.b16 {%0,%1,%2,%3}, [%4];"
                 : "=r"(r[0]), "=r"(r[1]), "=r"(r[2]), "=r"(r[3]) : "r"(addr));
}
__device__ __forceinline__ void mma_bf16(float* c, const uint32_t* a, uint32_t b0, uint32_t b1) {
    asm volatile("mma.sync.aligned.m16n8k16.row.col.f32.bf16.bf16.f32 "
                 "{%0,%1,%2,%3}, {%4,%5,%6,%7}, {%8,%9}, {%0,%1,%2,%3};"
                 : "+f"(c[0]), "+f"(c[1]), "+f"(c[2]), "+f"(c[3])
                 : "r"(a[0]), "r"(a[1]), "r"(a[2]), "r"(a[3]), "r"(b0), "r"(b1));
}

// swizzled 16B-unit offset inside a 128x32 bf16 tile
__device__ __forceinline__ uint32_t tile_off(int row, int c) {
    return (uint32_t)(((row << 2) + (c ^ ((row >> 1) & 3))) << 4);
}

// ---------------------------------------------------------------------------
// prep: fused bsplit (blocks [0,2048)) + hproj1 (blocks [2048,2304))
// ---------------------------------------------------------------------------
__global__ void prep_kernel(const float* __restrict__ W,
                            const float* __restrict__ hidden) {
    __shared__ float tile[32][33];
    const int bid = blockIdx.x;
    const int t = threadIdx.x;

    if (bid < 2048) {
        const int k0 = (bid & 63) * 32;
        const int n0 = (bid >> 6) * 32;
        const int tx = t & 31;
        const int ty = t >> 5;
#pragma unroll
        for (int r = 0; r < 4; r++) {
            int k = ty * 4 + r;
            tile[k][tx] = W[(size_t)(H_DIM + k0 + k) * H_DIM + n0 + tx];
        }
        __syncthreads();
#pragma unroll
        for (int r = 0; r < 4; r++) {
            int n = ty * 4 + r;
            float w = tile[tx][n];
            __nv_bfloat16 h = __float2bfloat16_rn(w);
            float l = w - __bfloat162float(h);
            size_t o = (size_t)(n0 + n) * K_DIM + k0 + tx;
            g_Bh[o] = h;
            g_Bl[o] = __float2bfloat16_rn(l);
        }
    } else {
        const int idx = bid - 2048;
        const int b  = idx & 31;
        const int sl = idx >> 5;
        const int h4 = t * 4;
        const float* hr = hidden + b * H_DIM + sl * 128;
        float4 acc = make_float4(0.f, 0.f, 0.f, 0.f);
#pragma unroll 8
        for (int e = 0; e < 128; e++) {
            float f = hr[e];
            float4 w = *reinterpret_cast<const float4*>(
                &W[(size_t)(sl * 128 + e) * H_DIM + h4]);
            acc.x += f * w.x; acc.y += f * w.y; acc.z += f * w.z; acc.w += f * w.w;
        }
        *reinterpret_cast<float4*>(&g_hpart[((size_t)sl * B_DIM + b) * H_DIM + h4]) = acc;
    }
}

// ---------------------------------------------------------------------------
// hproj stage 2: combine slices + bias, store transposed [h][b]
// ---------------------------------------------------------------------------
__global__ void hproj2_kernel(const float* __restrict__ bias) {
    int g = blockIdx.x * 256 + threadIdx.x;
    int b = g >> 8;
    int h4 = (g & 255) * 4;
    float4 acc = make_float4(bias[h4], bias[h4 + 1], bias[h4 + 2], bias[h4 + 3]);
#pragma unroll
    for (int sl = 0; sl < 8; sl++) {
        float4 p = *reinterpret_cast<const float4*>(
            &g_hpart[((size_t)sl * B_DIM + b) * H_DIM + h4]);
        acc.x += p.x; acc.y += p.y; acc.z += p.z; acc.w += p.w;
    }
    g_hprojT[(h4 + 0) * B_DIM + b] = acc.x;
    g_hprojT[(h4 + 1) * B_DIM + b] = acc.y;
    g_hprojT[(h4 + 2) * B_DIM + b] = acc.z;
    g_hprojT[(h4 + 3) * B_DIM + b] = acc.w;
}

// ---------------------------------------------------------------------------
// Pre-split A (enc, fp32) -> bf16 hi/lo
// ---------------------------------------------------------------------------
__global__ void asplit_kernel(const float* __restrict__ enc) {
    size_t g = ((size_t)blockIdx.x * 256 + threadIdx.x) * 8;
    float4 f0 = *reinterpret_cast<const float4*>(enc + g);
    float4 f1 = *reinterpret_cast<const float4*>(enc + g + 4);
    float x[8] = {f0.x, f0.y, f0.z, f0.w, f1.x, f1.y, f1.z, f1.w};
    uint32_t hh[4], ll[4];
#pragma unroll
    for (int i = 0; i < 4; i++) {
        __nv_bfloat162 h = __floats2bfloat162_rn(x[2 * i], x[2 * i + 1]);
        float2 hf = __bfloat1622float2(h);
        __nv_bfloat162 l = __floats2bfloat162_rn(x[2 * i] - hf.x, x[2 * i + 1] - hf.y);
        hh[i] = *reinterpret_cast<uint32_t*>(&h);
        ll[i] = *reinterpret_cast<uint32_t*>(&l);
    }
    *reinterpret_cast<uint4*>(&g_Ah[g]) = make_uint4(hh[0], hh[1], hh[2], hh[3]);
    *reinterpret_cast<uint4*>(&g_Al[g]) = make_uint4(ll[0], ll[1], ll[2], ll[3]);
}

// ---------------------------------------------------------------------------
// HMMA GEMM + fused tanh/v epilogue.
// grid (8 Ntiles, 512 Mtiles), 256 threads, 2 CTA/SM, 32x64 warp tiles.
// Mainloop restructured for low fragment liveness: A frags resident,
// B streamed per-n16 group (Bh pass: 8 MMA/group; Bl pass: 4 MMA/group).
// ---------------------------------------------------------------------------
__global__ __launch_bounds__(THREADS, 2)
void score_kernel(const float* __restrict__ v) {
    extern __shared__ char dsm[];
    const int tid  = threadIdx.x;
    const int wid  = tid >> 5;
    const int lane = tid & 31;
    const int Mo = blockIdx.y * BM;
    const int No = blockIdx.x * BN;

    const int wm = (wid & 3) * 32;
    const int wn = (wid >> 2) * 64;

    const int lrow = lane & 15, lk = lane >> 4;
    uint32_t aoff[2][2], boff[4][2];
#pragma unroll
    for (int ks = 0; ks < 2; ks++) {
#pragma unroll
        for (int mt = 0; mt < 2; mt++)
            aoff[mt][ks] = tile_off(wm + mt * 16 + lrow, ks * 2 + lk);
#pragma unroll
        for (int nb = 0; nb < 4; nb++)
            boff[nb][ks] = tile_off(wn + nb * 16 + lrow, ks * 2 + lk);
    }

    const char* pA[2];
    const char* pB[2];
    uint32_t so[2];
#pragma unroll
    for (int i = 0; i < 2; i++) {
        int idx = tid + i * 256;
        int row = idx >> 2, c = idx & 3;
        so[i] = tile_off(row, c);
        pA[i] = reinterpret_cast<const char*>(&g_Ah[(size_t)(Mo + row) * K_DIM + c * 8]);
        pB[i] = reinterpret_cast<const char*>(&g_Bh[(size_t)(No + row) * K_DIM + c * 8]);
    }
    const size_t dAL = (const char*)g_Al - (const char*)g_Ah;
    const size_t dBL = (const char*)g_Bl - (const char*)g_Bh;

    const uint32_t smb = smem_u32(dsm);
    float acc[2][8][4];
#pragma unroll
    for (int mt = 0; mt < 2; mt++)
#pragma unroll
        for (int nt = 0; nt < 8; nt++)
#pragma unroll
            for (int i = 0; i < 4; i++) acc[mt][nt][i] = 0.f;

    auto load_stage = [&](int slot) {
        uint32_t sb = smb + slot * STAGE_BYTES;
#pragma unroll
        for (int i = 0; i < 2; i++) {
            cp16(sb + PART_A_H + so[i], pA[i]);
            cp16(sb + PART_A_L + so[i], pA[i] + dAL);
            cp16(sb + PART_B_H + so[i], pB[i]);
            cp16(sb + PART_B_L + so[i], pB[i] + dBL);
        }
        pA[0] += 64; pA[1] += 64; pB[0] += 64; pB[1] += 64;
    };

    load_stage(0); cp_commit();
    load_stage(1); cp_commit();
    cp_wait1();
    __syncthreads();

    int slot_ld = 2, slot_cp = 0;
    for (int kt = 0; kt < KTILES; kt++) {
        if (kt + STAGES - 1 < KTILES) load_stage(slot_ld);
        cp_commit();
        if (++slot_ld == STAGES) slot_ld = 0;

        uint32_t AH = smb + slot_cp * STAGE_BYTES + PART_A_H;
        uint32_t AL = smb + slot_cp * STAGE_BYTES + PART_A_L;
        uint32_t BH = smb + slot_cp * STAGE_BYTES + PART_B_H;
        uint32_t BL = smb + slot_cp * STAGE_BYTES + PART_B_L;
        if (++slot_cp == STAGES) slot_cp = 0;

#pragma unroll
        for (int ks = 0; ks < 2; ks++) {
            // A fragments resident for the whole ks step (16 regs)
            uint32_t ah0[4], ah1[4], al0[4], al1[4];
            ldsm4(ah0, AH + aoff[0][ks]);
            ldsm4(ah1, AH + aoff[1][ks]);
            ldsm4(al0, AL + aoff[0][ks]);
            ldsm4(al1, AL + aoff[1][ks]);

            // Bh pass: stream 4 reg B group per n16, 8 MMA each (Ah + Al terms)
#pragma unroll
            for (int nb = 0; nb < 4; nb++) {
                uint32_t b[4];
                ldsm4(b, BH + boff[nb][ks]);
                mma_bf16(acc[0][2 * nb],     ah0, b[0], b[2]);
                mma_bf16(acc[0][2 * nb + 1], ah0, b[1], b[3]);
                mma_bf16(acc[1][2 * nb],     ah1, b[0], b[2]);
                mma_bf16(acc[1][2 * nb + 1], ah1, b[1], b[3]);
                mma_bf16(acc[0][2 * nb],     al0, b[0], b[2]);
                mma_bf16(acc[0][2 * nb + 1], al0, b[1], b[3]);
                mma_bf16(acc[1][2 * nb],     al1, b[0], b[2]);
                mma_bf16(acc[1][2 * nb + 1], al1, b[1], b[3]);
            }
            // Bl pass: 4 MMA per n16 group (Ah term only)
#pragma unroll
            for (int nb = 0; nb < 4; nb++) {
                uint32_t b[4];
                ldsm4(b, BL + boff[nb][ks]);
                mma_bf16(acc[0][2 * nb],     ah0, b[0], b[2]);
                mma_bf16(acc[0][2 * nb + 1], ah0, b[1], b[3]);
                mma_bf16(acc[1][2 * nb],     ah1, b[0], b[2]);
                mma_bf16(acc[1][2 * nb + 1], ah1, b[1], b[3]);
            }
        }
        cp_wait1();
        __syncthreads();
    }

    // ---- epilogue ----
    float* hp_s = reinterpret_cast<float*>(dsm);           // [128][33]
    float* v_s  = reinterpret_cast<float*>(dsm + 128 * 33 * 4);
    float* red  = v_s + 128;                               // [2][128]
    __syncthreads();
    for (int i = tid; i < 128 * 32; i += THREADS) {
        int nl = i >> 5, b = i & 31;
        hp_s[nl * 33 + b] = g_hprojT[(No + nl) * B_DIM + b];
    }
    if (tid < 128) v_s[tid] = v[No + tid];
    __syncthreads();

#pragma unroll
    for (int mt = 0; mt < 2; mt++) {
        int r0 = Mo + wm + mt * 16 + (lane >> 2);
        int b0r = r0 & 31, b1r = (r0 + 8) & 31;
        float s0 = 0.f, s1 = 0.f;
#pragma unroll
        for (int nt = 0; nt < 8; nt++) {
            int nl = wn + nt * 8 + (lane & 3) * 2;
            float vv0 = v_s[nl], vv1 = v_s[nl + 1];
            s0 += vv0 * tanhf(acc[mt][nt][0] + hp_s[nl * 33 + b0r]);
            s0 += vv1 * tanhf(acc[mt][nt][1] + hp_s[(nl + 1) * 33 + b0r]);
            s1 += vv0 * tanhf(acc[mt][nt][2] + hp_s[nl * 33 + b1r]);
            s1 += vv1 * tanhf(acc[mt][nt][3] + hp_s[(nl + 1) * 33 + b1r]);
        }
        s0 += __shfl_xor_sync(0xffffffffu, s0, 1);
        s0 += __shfl_xor_sync(0xffffffffu, s0, 2);
        s1 += __shfl_xor_sync(0xffffffffu, s1, 1);
        s1 += __shfl_xor_sync(0xffffffffu, s1, 2);
        if ((lane & 3) == 0) {
            int rl = wm + mt * 16 + (lane >> 2);
            red[(wid >> 2) * 128 + rl] = s0;
            red[(wid >> 2) * 128 + rl + 8] = s1;
        }
    }
    __syncthreads();
    if (tid < 128)
        g_part[(size_t)blockIdx.x * M_DIM + Mo + tid] = red[tid] + red[128 + tid];
}

// ---------------------------------------------------------------------------
// softmax: sum 8 N-tile partials, softmax over S per batch row
// ---------------------------------------------------------------------------
__global__ void softmax_kernel(float* __restrict__ out) {
    __shared__ float srow[S_DIM];
    __shared__ float rd[256];
    const int b = blockIdx.x;
    const int t = threadIdx.x;

    float m = -INFINITY;
    for (int i = t; i < S_DIM; i += 256) {
        int mm = i * B_DIM + b;
        float sc = 0.f;
#pragma unroll
        for (int nt = 0; nt < NTILES; nt++) sc += g_part[(size_t)nt * M_DIM + mm];
        srow[i] = sc;
        m = fmaxf(m, sc);
    }
    rd[t] = m;
    __syncthreads();
    for (int o = 128; o > 0; o >>= 1) { if (t < o) rd[t] = fmaxf(rd[t], rd[t + o]); __syncthreads(); }
    m = rd[0];
    __syncthreads();

    float sum = 0.f;
    for (int i = t; i < S_DIM; i += 256) {
        float e = expf(srow[i] - m);
        srow[i] = e;
        sum += e;
    }
    rd[t] = sum;
    __syncthreads();
    for (int o = 128; o > 0; o >>= 1) { if (t < o) rd[t] += rd[t + o]; __syncthreads(); }
    float inv = 1.f / rd[0];
    __syncthreads();
    float* orow = out + (size_t)b * S_DIM;
    for (int i = t; i < S_DIM; i += 256) orow[i] = srow[i] * inv;
}

// ---------------------------------------------------------------------------
extern "C" void kernel_launch(void* const* d_in, const int* in_sizes, int n_in,
                              void* d_out, int out_size) {
    const float* hidden = (const float*)d_in[0];
    const float* enc    = (const float*)d_in[1];
    const float* W      = (const float*)d_in[2];
    const float* bias   = (const float*)d_in[3];
    const float* v      = (const float*)d_in[4];
    float* out = (float*)d_out;

    cudaFuncSetAttribute(score_kernel, cudaFuncAttributeMaxDynamicSharedMemorySize, DSMEM_BYTES);

    prep_kernel<<<2304, 256>>>(W, hidden);                 // launch 0
    hproj2_kernel<<<32, 256>>>(bias);                      // launch 1
    asplit_kernel<<<M_DIM * K_DIM / 2048, 256>>>(enc);     // launch 2
    score_kernel<<<dim3(NTILES, M_DIM / BM), THREADS, DSMEM_BYTES>>>(v);  // launch 3 (profiled)
    softmax_kernel<<<B_DIM, 256>>>(out);                   // launch 4
}